// round 15
// baseline (speedup 1.0000x reference)
#include <cuda_runtime.h>
#include <cstdint>

// B=4, H=8, S=2048, D=8 fused attention. R15:
//  - ZERO LDG in inner loop: PV reads the same xt (transposed x tile) LDS registers
//    as QK, with accumulators packed over key-pairs (horizontal add at epilogue).
//  - projections algebraically folded (A=Wq^T Wk, u=Wq^T bk, z=Wk^T bq, c=bq.bk)
//  - QPT=2, TQ=256, 128 threads, KSPLIT=2 -> 512 CTAs, occ 3
//  - coalesced cp.async mask staging (double-buffered)

#define S_LEN    2048
#define D_DIM    8
#define NTHREADS 128
#define TQ       256          // queries per CTA (2 per thread)
#define TK       16           // keys per tile
#define KSPLIT   2
#define KEYS_PER (S_LEN / KSPLIT)        // 1024
#define MSTRIDE  20           // mask row stride (floats)
#define KSTRIDE  20           // xt row stride per d (floats)
#define NTILES   (KEYS_PER / TK)         // 64
#define NQ_TOT   (4 * 8 * S_LEN)         // 65536

typedef unsigned long long u64;

__device__ float g_m[KSPLIT][NQ_TOT];
__device__ float g_l[KSPLIT][NQ_TOT];
__device__ float g_acc[KSPLIT][NQ_TOT][D_DIM];

__device__ __forceinline__ float ex2f(float x) {
    float r; asm("ex2.approx.ftz.f32 %0, %1;" : "=f"(r) : "f"(x)); return r;
}
__device__ __forceinline__ u64 fma2(u64 a, u64 b, u64 c) {
    u64 r; asm("fma.rn.f32x2 %0, %1, %2, %3;" : "=l"(r) : "l"(a), "l"(b), "l"(c)); return r;
}
__device__ __forceinline__ u64 mul2(u64 a, u64 b) {
    u64 r; asm("mul.rn.f32x2 %0, %1, %2;" : "=l"(r) : "l"(a), "l"(b)); return r;
}
__device__ __forceinline__ u64 add2(u64 a, u64 b) {
    u64 r; asm("add.rn.f32x2 %0, %1, %2;" : "=l"(r) : "l"(a), "l"(b)); return r;
}
__device__ __forceinline__ u64 pk2(float lo, float hi) {
    u64 r; asm("mov.b64 %0, {%1, %2};" : "=l"(r) : "f"(lo), "f"(hi)); return r;
}
__device__ __forceinline__ void up2(u64 v, float& lo, float& hi) {
    asm("mov.b64 {%0, %1}, %2;" : "=f"(lo), "=f"(hi) : "l"(v));
}
__device__ __forceinline__ uint32_t s2u(const void* p) {
    uint32_t a;
    asm("{ .reg .u64 t; cvta.to.shared.u64 t, %1; cvt.u32.u64 %0, t; }" : "=r"(a) : "l"(p));
    return a;
}
__device__ __forceinline__ void cp16(uint32_t dst, const void* src) {
    asm volatile("cp.async.cg.shared.global [%0], [%1], 16;" :: "r"(dst), "l"(src));
}
__device__ __forceinline__ void cpcommit() { asm volatile("cp.async.commit_group;"); }
__device__ __forceinline__ void cpwait0() { asm volatile("cp.async.wait_group 0;"); }

__global__ __launch_bounds__(NTHREADS, 3)
void attn_r15_partial(const float* __restrict__ x,     // [B,H,S,D]
                      const float* __restrict__ mask,  // [B,1,S,S]
                      const float* __restrict__ Wq,    // [D,D]
                      const float* __restrict__ bq,    // [D]
                      const float* __restrict__ Wk,    // [D,D]
                      const float* __restrict__ bk)    // [D]
{
    extern __shared__ float smem[];
    float* mk  = smem;                        // [2 * TQ * MSTRIDE] = 10240 floats
    float* xt  = mk + 2 * TQ * MSTRIDE;       // [2 * D_DIM * KSTRIDE] = 320 floats
    float* A_s = xt + 2 * D_DIM * KSTRIDE;    // 64
    float* z_s = A_s + 64;                    // 8
    float* u_s = z_s + 8;                     // 8
    float* c_s = u_s + 8;                     // 8 (1 used)

    const int t  = threadIdx.x;
    const int qt = blockIdx.x;
    const int h  = blockIdx.y;
    const int b  = blockIdx.z >> 1;
    const int ks = blockIdx.z & 1;
    const int kbase = ks * KEYS_PER;

    const float* xb = x + ((size_t)(b * 8 + h) * S_LEN) * D_DIM;  // [S, D]
    const float* mb = mask + (size_t)b * S_LEN * S_LEN;           // [S, S]
    const int qbase = qt * TQ;

    // ---- fold projections: A = Wq^T Wk, u = Wq^T bk, z = Wk^T bq, c = bq.bk ----
    if (t < 64) {
        int e = t >> 3, f = t & 7;
        float a = 0.f;
        #pragma unroll
        for (int d = 0; d < 8; d++) a = fmaf(Wq[d * 8 + e], Wk[d * 8 + f], a);
        A_s[e * 8 + f] = a;
        if (t < 8) {
            float uu = 0.f, zz = 0.f;
            #pragma unroll
            for (int d = 0; d < 8; d++) {
                uu = fmaf(Wq[d * 8 + t], bk[d], uu);
                zz = fmaf(bq[d], Wk[d * 8 + t], zz);
            }
            u_s[t] = uu; z_s[t] = zz;
        }
        if (t == 0) {
            float cc = 0.f;
            #pragma unroll
            for (int d = 0; d < 8; d++) cc = fmaf(bq[d], bk[d], cc);
            c_s[0] = cc;
        }
    }

    const uint32_t mk_u32 = s2u(mk);

    // ---- prefetch mask tile 0 (256 rows x 4 cp16 = 1024, 8/thread) ----
    {
        #pragma unroll
        for (int i = 0; i < 8; i++) {
            int idx = t + i * NTHREADS;
            int row = idx >> 2;
            int c4  = idx & 3;
            cp16(mk_u32 + (uint32_t)(row * MSTRIDE + c4 * 4) * 4,
                 mb + (size_t)(qbase + row) * S_LEN + kbase + c4 * 4);
        }
        cpcommit();
    }
    // ---- stage x-transpose tile 0: xt[d][key], 1 value/thread ----
    {
        int d = t & 7, key = t >> 3;          // consecutive threads -> contiguous gmem
        xt[d * KSTRIDE + key] = xb[(size_t)(kbase + key) * D_DIM + d];
    }
    __syncthreads();   // A_s/z_s/u_s/c_s + xt tile 0 visible

    // ---- per-query y_hat (splatted) and c_hat ----
    const float LOG2E = 1.4426950408889634f;
    const float QS    = LOG2E * 0.35355339059327373f;   // log2e / sqrt(8)
    const float MC    = -10000.0f * LOG2E;
    const u64  MC2    = pk2(MC, MC);

    u64 qA[8], qB[8], cA2, cB2;
    #pragma unroll
    for (int w = 0; w < 2; w++) {
        int qi = qbase + t + w * 128;
        const float4* xr = (const float4*)(xb + (size_t)qi * D_DIM);
        float4 a0 = xr[0], a1 = xr[1];
        float xv[8] = {a0.x, a0.y, a0.z, a0.w, a1.x, a1.y, a1.z, a1.w};
        u64* qq = w ? qB : qA;
        #pragma unroll
        for (int f = 0; f < 8; f++) {
            float acc = z_s[f];
            #pragma unroll
            for (int e = 0; e < 8; e++)
                acc = fmaf(xv[e], A_s[e * 8 + f], acc);
            acc *= QS;
            qq[f] = pk2(acc, acc);
        }
        float ch = c_s[0];
        #pragma unroll
        for (int e = 0; e < 8; e++) ch = fmaf(xv[e], u_s[e], ch);
        ch *= QS;
        if (w) cB2 = pk2(ch, ch); else cA2 = pk2(ch, ch);
    }

    // ---- online softmax over this CTA's 1024 keys ----
    // accumulators packed over key-pairs: accX_d holds (sum over even keys, odd keys)
    float mA = -1e30f, lA = 0.0f, mB = -1e30f, lB = 0.0f;
    u64 nmA2 = pk2(1e30f, 1e30f), nmB2 = nmA2;
    u64 accA[8], accB[8];
    #pragma unroll
    for (int d = 0; d < 8; d++) { accA[d] = 0; accB[d] = 0; }

    for (int tile = 0; tile < NTILES; tile++) {
        const int buf = tile & 1;
        cpwait0();
        __syncthreads();

        if (tile + 1 < NTILES) {
            const int nbuf = buf ^ 1;
            const int nkb  = kbase + (tile + 1) * TK;
            #pragma unroll
            for (int i = 0; i < 8; i++) {
                int idx = t + i * NTHREADS;
                int row = idx >> 2;
                int c4  = idx & 3;
                cp16(mk_u32 + (uint32_t)((nbuf * TQ + row) * MSTRIDE + c4 * 4) * 4,
                     mb + (size_t)(qbase + row) * S_LEN + nkb + c4 * 4);
            }
            cpcommit();
            int d = t & 7, key = t >> 3;
            xt[nbuf * D_DIM * KSTRIDE + d * KSTRIDE + key] =
                xb[(size_t)(nkb + key) * D_DIM + d];
        }

        const float* xtb   = xt + buf * D_DIM * KSTRIDE;
        const float* mrowA = mk + (buf * TQ + t) * MSTRIDE;
        const float* mrowB = mrowA + 128 * MSTRIDE;

        #pragma unroll
        for (int g = 0; g < TK / 4; g++) {
            // x quads: per d, (x_d[4g..4g+3]) as 2 packed pairs (broadcast LDS.128)
            // -> used for BOTH the QK dot products and the PV accumulation
            u64 kq0[8], kq1[8];
            #pragma unroll
            for (int d = 0; d < 8; d++) {
                ulonglong2 kk = *(const ulonglong2*)(xtb + d * KSTRIDE + g * 4);
                kq0[d] = kk.x;
                kq1[d] = kk.y;
            }
            ulonglong2 mqA = *(const ulonglong2*)(mrowA + g * 4);
            ulonglong2 mqB = *(const ulonglong2*)(mrowB + g * 4);

            u64 s01A = fma2(qA[0], kq0[0], cA2);
            u64 s23A = fma2(qA[0], kq1[0], cA2);
            u64 s01B = fma2(qB[0], kq0[0], cB2);
            u64 s23B = fma2(qB[0], kq1[0], cB2);
            #pragma unroll
            for (int d = 1; d < 8; d++) {
                s01A = fma2(qA[d], kq0[d], s01A);
                s23A = fma2(qA[d], kq1[d], s23A);
                s01B = fma2(qB[d], kq0[d], s01B);
                s23B = fma2(qB[d], kq1[d], s23B);
            }
            s01A = fma2(mqA.x, MC2, s01A);
            s23A = fma2(mqA.y, MC2, s23A);
            s01B = fma2(mqB.x, MC2, s01B);
            s23B = fma2(mqB.y, MC2, s23B);

            float s0A, s1A, s2A, s3A, s0B, s1B, s2B, s3B;
            up2(s01A, s0A, s1A); up2(s23A, s2A, s3A);
            up2(s01B, s0B, s1B); up2(s23B, s2B, s3B);

            float gA = fmaxf(fmaxf(s0A, s1A), fmaxf(s2A, s3A));
            if (__builtin_expect(gA > mA, 0)) {
                float c = ex2f(mA - gA); mA = gA; lA *= c;
                nmA2 = pk2(-mA, -mA);
                u64 c2 = pk2(c, c);
                #pragma unroll
                for (int d = 0; d < 8; d++) accA[d] = mul2(accA[d], c2);
            }
            float gB = fmaxf(fmaxf(s0B, s1B), fmaxf(s2B, s3B));
            if (__builtin_expect(gB > mB, 0)) {
                float c = ex2f(mB - gB); mB = gB; lB *= c;
                nmB2 = pk2(-mB, -mB);
                u64 c2 = pk2(c, c);
                #pragma unroll
                for (int d = 0; d < 8; d++) accB[d] = mul2(accB[d], c2);
            }

            u64 d01A = add2(s01A, nmA2), d23A = add2(s23A, nmA2);
            u64 d01B = add2(s01B, nmB2), d23B = add2(s23B, nmB2);
            float e0A, e1A, e2A, e3A, e0B, e1B, e2B, e3B;
            up2(d01A, e0A, e1A); up2(d23A, e2A, e3A);
            up2(d01B, e0B, e1B); up2(d23B, e2B, e3B);
            float p0A = ex2f(e0A), p1A = ex2f(e1A), p2A = ex2f(e2A), p3A = ex2f(e3A);
            float p0B = ex2f(e0B), p1B = ex2f(e1B), p2B = ex2f(e2B), p3B = ex2f(e3B);
            lA += p0A + p1A + p2A + p3A;
            lB += p0B + p1B + p2B + p3B;

            // PV from the SAME kq registers (no loads): packed over key-pairs
            u64 p01A = pk2(p0A, p1A), p23A = pk2(p2A, p3A);
            u64 p01B = pk2(p0B, p1B), p23B = pk2(p2B, p3B);
            #pragma unroll
            for (int d = 0; d < 8; d++) {
                accA[d] = fma2(p01A, kq0[d], accA[d]);
                accA[d] = fma2(p23A, kq1[d], accA[d]);
                accB[d] = fma2(p01B, kq0[d], accB[d]);
                accB[d] = fma2(p23B, kq1[d], accB[d]);
            }
        }
    }

    // ---- write unnormalized partials (horizontal add of packed accs) ----
    const int qid0 = (b * 8 + h) * S_LEN + qbase + t;        // query A
    {
        float o[8];
        #pragma unroll
        for (int d = 0; d < 8; d++) { float lo, hi; up2(accA[d], lo, hi); o[d] = lo + hi; }
        g_m[ks][qid0] = mA;
        g_l[ks][qid0] = lA;
        float4* pa = (float4*)g_acc[ks][qid0];
        pa[0] = make_float4(o[0], o[1], o[2], o[3]);
        pa[1] = make_float4(o[4], o[5], o[6], o[7]);
    }
    const int qid1 = qid0 + 128;                              // query B
    {
        float o[8];
        #pragma unroll
        for (int d = 0; d < 8; d++) { float lo, hi; up2(accB[d], lo, hi); o[d] = lo + hi; }
        g_m[ks][qid1] = mB;
        g_l[ks][qid1] = lB;
        float4* pb = (float4*)g_acc[ks][qid1];
        pb[0] = make_float4(o[0], o[1], o[2], o[3]);
        pb[1] = make_float4(o[4], o[5], o[6], o[7]);
    }
}

__global__ __launch_bounds__(256)
void attn_r15_reduce(float* __restrict__ out)   // [B,H,S,D] flat: qid*8+d
{
    const int qid = blockIdx.x * 256 + threadIdx.x;

    float m0 = g_m[0][qid], m1 = g_m[1][qid];
    float l0 = g_l[0][qid], l1 = g_l[1][qid];
    float M  = fmaxf(m0, m1);
    float c0 = ex2f(m0 - M);     // m is log2-domain
    float c1 = ex2f(m1 - M);
    float inv = 1.0f / (l0 * c0 + l1 * c1);
    float w0 = c0 * inv, w1 = c1 * inv;

    const float4* a0 = (const float4*)g_acc[0][qid];
    const float4* a1 = (const float4*)g_acc[1][qid];
    float4 x0 = a0[0], x1 = a0[1];
    float4 y0 = a1[0], y1 = a1[1];

    float4* orow = (float4*)(out + (size_t)qid * D_DIM);
    orow[0] = make_float4(x0.x * w0 + y0.x * w1, x0.y * w0 + y0.y * w1,
                          x0.z * w0 + y0.z * w1, x0.w * w0 + y0.w * w1);
    orow[1] = make_float4(x1.x * w0 + y1.x * w1, x1.y * w0 + y1.y * w1,
                          x1.z * w0 + y1.z * w1, x1.w * w0 + y1.w * w1);
}

extern "C" void kernel_launch(void* const* d_in, const int* in_sizes, int n_in,
                              void* d_out, int out_size) {
    const float* x    = (const float*)d_in[0];
    const float* mask = (const float*)d_in[1];
    const float* Wq   = (const float*)d_in[2];
    const float* bq   = (const float*)d_in[3];
    const float* Wk   = (const float*)d_in[4];
    const float* bk   = (const float*)d_in[5];
    float* out = (float*)d_out;

    const int smem_bytes = (2 * TQ * MSTRIDE + 2 * D_DIM * KSTRIDE + 64 + 8 + 8 + 8)
                           * sizeof(float);

    cudaFuncSetAttribute(attn_r15_partial,
                         cudaFuncAttributeMaxDynamicSharedMemorySize, smem_bytes);

    dim3 grid(S_LEN / TQ, 8, 4 * KSPLIT);   // (8 qt, 8 h, 8 b*ks) = 512 CTAs
    dim3 block(NTHREADS);
    attn_r15_partial<<<grid, block, smem_bytes>>>(x, mask, Wq, bq, Wk, bk);

    attn_r15_reduce<<<NQ_TOT / 256, 256>>>(out);
}